// round 4
// baseline (speedup 1.0000x reference)
#include <cuda_runtime.h>
#include <math.h>

#define NU 208
#define NV 176
#define NIMG 256
#define NUV (NU * NV)            // 36608
#define MALL (NIMG * NU)         // 53248
#define TW 352                   // width of T / Q (Re|Im interleaved)
#define GK 416                   // stacked [Re;Im] height
#define RANK 18303               // jax 'nearest' resolves 18303.5 -> 18303
#define KEXCL 18304              // exclude exactly this many (<= thr)

// ---------------- static device scratch (no allocs allowed) ----------------
static __device__ float g_E1[NV * TW];       // [v][k]: k<176 -> Cv, else -Sv
static __device__ float g_E2r[TW * NV];      // [kk][v]: kk<176 -> Cv, else -Sv
static __device__ float g_E2i[TW * NV];      // [kk][v]: kk<176 -> Sv, else  Cv
static __device__ float g_Gz[GK * GK];       // [[Cu, Su],[-Su, Cu]]
static __device__ float g_Gq[GK * GK];       // [[Cu,-Su],[ Su, Cu]]
static __device__ float g_r[NUV];
static __device__ float g_mask[NUV];
static __device__ float g_thr;
static __device__ unsigned g_cless;
static __device__ float g_T[(size_t)MALL * TW];       // 75 MB
static __device__ float g_P[(size_t)NIMG * GK * NV];  // 75 MB
static __device__ float g_Q[(size_t)MALL * TW];       // 75 MB

// ---------------- exact-ish trig helpers (double, argument-reduced) --------
__device__ __forceinline__ float tcos(int num, int den) {
    double a = 2.0 * (double)(num % den) / (double)den;
    return (float)cospi(a);
}
__device__ __forceinline__ float tsin(int num, int den) {
    double a = 2.0 * (double)(num % den) / (double)den;
    return (float)sinpi(a);
}

// ---------------- constant table builder -----------------------------------
__global__ void k_tables() {
    const int total = NV * TW + 2 * TW * NV + 2 * GK * GK;
    for (int idx = blockIdx.x * blockDim.x + threadIdx.x; idx < total;
         idx += gridDim.x * blockDim.x) {
        int i = idx;
        if (i < NV * TW) {  // E1 [v][k]
            int v = i / TW, k = i % TW;
            g_E1[i] = (k < NV) ? tcos(v * k, NV) : -tsin(v * (k - NV), NV);
            continue;
        }
        i -= NV * TW;
        if (i < TW * NV) {  // E2r [kk][v]
            int kk = i / NV, v = i % NV;
            g_E2r[i] = (kk < NV) ? tcos(kk * v, NV) : -tsin((kk - NV) * v, NV);
            continue;
        }
        i -= TW * NV;
        if (i < TW * NV) {  // E2i [kk][v]
            int kk = i / NV, v = i % NV;
            g_E2i[i] = (kk < NV) ? tsin(kk * v, NV) : tcos((kk - NV) * v, NV);
            continue;
        }
        i -= TW * NV;
        if (i < GK * GK) {  // Gz
            int m = i / GK, kk = i % GK;
            int l = (m < NU) ? m : m - NU;
            int u = (kk < NU) ? kk : kk - NU;
            float c = tcos(l * u, NU), s = tsin(l * u, NU);
            g_Gz[i] = (m < NU) ? ((kk < NU) ? c : s) : ((kk < NU) ? -s : c);
            continue;
        }
        i -= GK * GK;
        {   // Gq
            int m = i / GK, kk = i % GK;
            int l = (m < NU) ? m : m - NU;
            int u = (kk < NU) ? kk : kk - NU;
            float c = tcos(l * u, NU), s = tsin(l * u, NU);
            g_Gq[i] = (m < NU) ? ((kk < NU) ? c : -s) : ((kk < NU) ? s : c);
        }
    }
}

// ---------------- r = Re(dft2d(sk2d)), canonicalized over the exact
// (l,k) <-> (-l,-k) degeneracy so conjugate partners are bit-identical ------
__global__ void k_r(const float* __restrict__ kern) {
    int idx = blockIdx.x * blockDim.x + threadIdx.x;
    if (idx >= NUV) return;
    int l = idx / NV, k = idx % NV;
    int lp = (NU - l) % NU, kp = (NV - k) % NV;
    if (lp < l || (lp == l && kp < k)) { l = lp; k = kp; }
    double s = 0.0;
#pragma unroll
    for (int m = 0; m < 6; ++m) {
#pragma unroll
        for (int n = 0; n < 6; ++n) {
            int km = (m < 3) ? m : 5 - m;  // sk2d symmetric tiling
            int kn = (n < 3) ? n : 5 - n;
            float p = kern[km * 3 + kn];
            double ang = 2.0 * ((double)((k * m) % NV) / (double)NV +
                                (double)((l * n) % NU) / (double)NU);
            s += (double)p * cospi(ang);
        }
    }
    g_r[idx] = (float)(s / 36.0);
}

// ---------------- exact k-th order statistic (radix select) ----------------
__device__ __forceinline__ unsigned key_of(float f) {
    unsigned u = __float_as_uint(f);
    return (u & 0x80000000u) ? ~u : (u | 0x80000000u);
}

__global__ void k_select() {
    __shared__ unsigned hist[256];
    __shared__ unsigned s_prefix, s_want;
    if (threadIdx.x == 0) { s_prefix = 0u; s_want = (unsigned)RANK; }
    __syncthreads();
    for (int pass = 0; pass < 4; ++pass) {
        int shift = 24 - 8 * pass;
        hist[threadIdx.x] = 0u;
        __syncthreads();
        unsigned prefix = s_prefix;
        unsigned hmask = (pass == 0) ? 0u : (0xFFFFFFFFu << (shift + 8));
        for (int i = threadIdx.x; i < NUV; i += 256) {
            unsigned key = key_of(g_r[i]);
            if ((key & hmask) == (prefix & hmask))
                atomicAdd(&hist[(key >> shift) & 255u], 1u);
        }
        __syncthreads();
        if (threadIdx.x == 0) {
            unsigned want = s_want, cum = 0; int b = 0;
            for (; b < 256; ++b) {
                if (cum + hist[b] > want) break;
                cum += hist[b];
            }
            s_prefix = prefix | ((unsigned)b << shift);
            s_want = want - cum;
        }
        __syncthreads();
    }
    if (threadIdx.x == 0) {
        unsigned kf = s_prefix;
        g_thr = __uint_as_float((kf & 0x80000000u) ? (kf ^ 0x80000000u) : ~kf);
        g_cless = 0u;  // reset for k_count (stream-ordered, graph-safe)
    }
}

// count strictly-less-than-threshold elements
__global__ void k_count() {
    int idx = blockIdx.x * blockDim.x + threadIdx.x;
    if (idx >= NUV) return;
    float thr = g_thr;
    unsigned ballot = __ballot_sync(0xFFFFFFFFu, g_r[idx] < thr);
    if ((threadIdx.x & 31) == 0) atomicAdd(&g_cless, (unsigned)__popc(ballot));
}

// mask: exclude exactly KEXCL smallest; among exact ties at thr, exclude the
// lowest-linear-index ones first (output-invariant: ties are conjugate pairs)
__global__ void k_mask() {
    int idx = blockIdx.x * blockDim.x + threadIdx.x;
    if (idx >= NUV) return;
    float thr = g_thr;
    float v = g_r[idx];
    float m;
    if (v > thr) m = 1.f;
    else if (v < thr) m = 0.f;
    else {
        int budget = (int)(KEXCL - g_cless);  // #ties to exclude
        int rank = 0;                          // my rank among tied elements
        for (int j = 0; j < idx; ++j)
            if (g_r[j] == thr) ++rank;
        m = (rank >= budget) ? 1.f : 0.f;
    }
    g_mask[idx] = m;
}

// ---------------- tiled fp32 GEMM stages -----------------------------------
#define BM 64
#define BN 64
#define BK 16

// Stage 1: T[53248 x 352] = X[53248 x 176] * E1[176 x 352]
__global__ void __launch_bounds__(256) k_gemm1(const float* __restrict__ X) {
    __shared__ float As[BK][BM];
    __shared__ float Bs[BK][BN];
    const int n0 = blockIdx.x * BN;
    const int m0 = blockIdx.y * BM;
    const int t = threadIdx.x;
    const int tx = t & 15, ty = t >> 4;
    float acc[4][4] = {};
    for (int k0 = 0; k0 < NV; k0 += BK) {
#pragma unroll
        for (int j = 0; j < 4; ++j) {
            int idx = t + 256 * j;
            int m = idx >> 4, kk = idx & 15;
            As[kk][m] = X[(size_t)(m0 + m) * NV + (k0 + kk)];
        }
#pragma unroll
        for (int j = 0; j < 4; ++j) {
            int idx = t + 256 * j;
            int kk = idx >> 6, n = idx & 63;
            int gn = n0 + n;
            Bs[kk][n] = (gn < TW) ? g_E1[(k0 + kk) * TW + gn] : 0.f;
        }
        __syncthreads();
#pragma unroll
        for (int kk = 0; kk < BK; ++kk) {
            float4 a4 = *(const float4*)&As[kk][ty * 4];
            float4 b4 = *(const float4*)&Bs[kk][tx * 4];
            float av[4] = {a4.x, a4.y, a4.z, a4.w};
            float bv[4] = {b4.x, b4.y, b4.z, b4.w};
#pragma unroll
            for (int i = 0; i < 4; ++i)
#pragma unroll
                for (int jj = 0; jj < 4; ++jj) acc[i][jj] += av[i] * bv[jj];
        }
        __syncthreads();
    }
#pragma unroll
    for (int i = 0; i < 4; ++i) {
        int gm = m0 + ty * 4 + i;
#pragma unroll
        for (int jj = 0; jj < 4; ++jj) {
            int gn = n0 + tx * 4 + jj;
            if (gn < TW) g_T[(size_t)gm * TW + gn] = acc[i][jj];
        }
    }
}

// Stage 2: per image P[416x176] = mask o ( Gz[416x416] * [Tr;Ti][416x176] )
__global__ void __launch_bounds__(256) k_gemm2() {
    __shared__ float As[BK][BM];
    __shared__ float Bs[BK][BN];
    const int img = blockIdx.z;
    const int n0 = blockIdx.x * BN;
    const int m0 = blockIdx.y * BM;
    const int t = threadIdx.x;
    const int tx = t & 15, ty = t >> 4;
    float acc[4][4] = {};
    for (int k0 = 0; k0 < GK; k0 += BK) {
#pragma unroll
        for (int j = 0; j < 4; ++j) {
            int idx = t + 256 * j;
            int m = idx >> 4, kk = idx & 15;
            int gm = m0 + m;
            As[kk][m] = (gm < GK) ? g_Gz[gm * GK + (k0 + kk)] : 0.f;
        }
#pragma unroll
        for (int j = 0; j < 4; ++j) {
            int idx = t + 256 * j;
            int kk = idx >> 6, n = idx & 63;
            int kg = k0 + kk;
            int gn = n0 + n;
            float bv = 0.f;
            if (gn < NV) {
                bv = (kg < NU)
                         ? g_T[((size_t)img * NU + kg) * TW + gn]
                         : g_T[((size_t)img * NU + kg - NU) * TW + NV + gn];
            }
            Bs[kk][n] = bv;
        }
        __syncthreads();
#pragma unroll
        for (int kk = 0; kk < BK; ++kk) {
            float4 a4 = *(const float4*)&As[kk][ty * 4];
            float4 b4 = *(const float4*)&Bs[kk][tx * 4];
            float av[4] = {a4.x, a4.y, a4.z, a4.w};
            float bv[4] = {b4.x, b4.y, b4.z, b4.w};
#pragma unroll
            for (int i = 0; i < 4; ++i)
#pragma unroll
                for (int jj = 0; jj < 4; ++jj) acc[i][jj] += av[i] * bv[jj];
        }
        __syncthreads();
    }
#pragma unroll
    for (int i = 0; i < 4; ++i) {
        int gm = m0 + ty * 4 + i;
        if (gm >= GK) continue;
        int l = (gm < NU) ? gm : gm - NU;
#pragma unroll
        for (int jj = 0; jj < 4; ++jj) {
            int gn = n0 + tx * 4 + jj;
            if (gn < NV)
                g_P[((size_t)img * GK + gm) * NV + gn] =
                    acc[i][jj] * g_mask[l * NV + gn];
        }
    }
}

// Stage 3: per image Q = Gq[416x416] * P[416x176], stored interleaved 208x352
__global__ void __launch_bounds__(256) k_gemm3() {
    __shared__ float As[BK][BM];
    __shared__ float Bs[BK][BN];
    const int img = blockIdx.z;
    const int n0 = blockIdx.x * BN;
    const int m0 = blockIdx.y * BM;
    const int t = threadIdx.x;
    const int tx = t & 15, ty = t >> 4;
    float acc[4][4] = {};
    for (int k0 = 0; k0 < GK; k0 += BK) {
#pragma unroll
        for (int j = 0; j < 4; ++j) {
            int idx = t + 256 * j;
            int m = idx >> 4, kk = idx & 15;
            int gm = m0 + m;
            As[kk][m] = (gm < GK) ? g_Gq[gm * GK + (k0 + kk)] : 0.f;
        }
#pragma unroll
        for (int j = 0; j < 4; ++j) {
            int idx = t + 256 * j;
            int kk = idx >> 6, n = idx & 63;
            int kg = k0 + kk;
            int gn = n0 + n;
            Bs[kk][n] =
                (gn < NV) ? g_P[((size_t)img * GK + kg) * NV + gn] : 0.f;
        }
        __syncthreads();
#pragma unroll
        for (int kk = 0; kk < BK; ++kk) {
            float4 a4 = *(const float4*)&As[kk][ty * 4];
            float4 b4 = *(const float4*)&Bs[kk][tx * 4];
            float av[4] = {a4.x, a4.y, a4.z, a4.w};
            float bv[4] = {b4.x, b4.y, b4.z, b4.w};
#pragma unroll
            for (int i = 0; i < 4; ++i)
#pragma unroll
                for (int jj = 0; jj < 4; ++jj) acc[i][jj] += av[i] * bv[jj];
        }
        __syncthreads();
    }
#pragma unroll
    for (int i = 0; i < 4; ++i) {
        int gm = m0 + ty * 4 + i;
        if (gm >= GK) continue;
        int uu = (gm < NU) ? gm : gm - NU;
#pragma unroll
        for (int jj = 0; jj < 4; ++jj) {
            int gn = n0 + tx * 4 + jj;
            if (gn < NV) {
                int col = (gm < NU) ? gn : gn + NV;
                g_Q[((size_t)img * NU + uu) * TW + col] = acc[i][jj];
            }
        }
    }
}

// Stage 4: out = sqrt(Yr^2+Yi^2)/(U*V);  Yr = Q*E2r,  Yi = Q*E2i
__global__ void __launch_bounds__(256) k_gemm4(float* __restrict__ out) {
    __shared__ float As[BK][BM];
    __shared__ float Br[BK][BN];
    __shared__ float Bi[BK][BN];
    const int n0 = blockIdx.x * BN;
    const int m0 = blockIdx.y * BM;
    const int t = threadIdx.x;
    const int tx = t & 15, ty = t >> 4;
    float ar[4][4] = {};
    float ai[4][4] = {};
    for (int k0 = 0; k0 < TW; k0 += BK) {
#pragma unroll
        for (int j = 0; j < 4; ++j) {
            int idx = t + 256 * j;
            int m = idx >> 4, kk = idx & 15;
            As[kk][m] = g_Q[(size_t)(m0 + m) * TW + (k0 + kk)];
        }
#pragma unroll
        for (int j = 0; j < 4; ++j) {
            int idx = t + 256 * j;
            int kk = idx >> 6, n = idx & 63;
            int gn = n0 + n;
            float br = 0.f, bi = 0.f;
            if (gn < NV) {
                br = g_E2r[(k0 + kk) * NV + gn];
                bi = g_E2i[(k0 + kk) * NV + gn];
            }
            Br[kk][n] = br;
            Bi[kk][n] = bi;
        }
        __syncthreads();
#pragma unroll
        for (int kk = 0; kk < BK; ++kk) {
            float4 a4 = *(const float4*)&As[kk][ty * 4];
            float4 r4 = *(const float4*)&Br[kk][tx * 4];
            float4 i4 = *(const float4*)&Bi[kk][tx * 4];
            float av[4] = {a4.x, a4.y, a4.z, a4.w};
            float rv[4] = {r4.x, r4.y, r4.z, r4.w};
            float iv[4] = {i4.x, i4.y, i4.z, i4.w};
#pragma unroll
            for (int i = 0; i < 4; ++i)
#pragma unroll
                for (int jj = 0; jj < 4; ++jj) {
                    ar[i][jj] += av[i] * rv[jj];
                    ai[i][jj] += av[i] * iv[jj];
                }
        }
        __syncthreads();
    }
    const float scale = 1.0f / (float)NUV;
#pragma unroll
    for (int i = 0; i < 4; ++i) {
        int gm = m0 + ty * 4 + i;
#pragma unroll
        for (int jj = 0; jj < 4; ++jj) {
            int gn = n0 + tx * 4 + jj;
            if (gn < NV) {
                float yr = ar[i][jj], yi = ai[i][jj];
                out[(size_t)gm * NV + gn] = sqrtf(yr * yr + yi * yi) * scale;
            }
        }
    }
}

// ---------------- launch -----------------------------------------------------
extern "C" void kernel_launch(void* const* d_in, const int* in_sizes, int n_in,
                              void* d_out, int out_size) {
    const float* x = nullptr;
    const float* kern = nullptr;
    for (int i = 0; i < n_in; ++i) {
        if (in_sizes[i] == 32 * 8 * NU * NV) x = (const float*)d_in[i];
        else if (in_sizes[i] == 9) kern = (const float*)d_in[i];
    }
    float* out = (float*)d_out;

    k_tables<<<512, 256>>>();
    k_r<<<(NUV + 255) / 256, 256>>>(kern);
    k_select<<<1, 256>>>();
    k_count<<<(NUV + 255) / 256, 256>>>();
    k_mask<<<(NUV + 255) / 256, 256>>>();

    k_gemm1<<<dim3(6, MALL / 64), 256>>>(x);
    k_gemm2<<<dim3(3, 7, NIMG), 256>>>();
    k_gemm3<<<dim3(3, 7, NIMG), 256>>>();
    k_gemm4<<<dim3(3, MALL / 64), 256>>>(out);
}

// round 5
// speedup vs baseline: 1.7999x; 1.7999x over previous
#include <cuda_runtime.h>
#include <math.h>

#define NU 208
#define NV 176
#define NIMG 256
#define NUV (NU * NV)            // 36608
#define MALL (NIMG * NU)         // 53248
#define KH 89                    // unique v-frequencies (0..88)
#define TW2 178                  // 2*KH (Re | Im)
#define NC (NIMG * KH)           // 22784 batched columns
#define GK 416                   // stacked [Re;Im] u-rows
#define QW 192                   // padded row stride of Q (178 -> 192)
#define RANK 18303               // jax 'nearest' resolves 18303.5 -> 18303
#define KEXCL 18304              // exclude exactly this many (<= thr)

// ---------------- static device scratch (no allocs allowed) ----------------
static __device__ float g_E1[NV * TW2];      // [v][j]: j<89 cos, else -sin
static __device__ float g_E4[QW * NV];       // [kk][v]; rows >=178 stay zero
static __device__ float g_Gz[GK * GK];       // [[C, S],[-S, C]]  (forward u)
static __device__ float g_Gq[GK * GK];       // [[C,-S],[ S, C]]  (inverse u)
static __device__ float g_r[NUV];
static __device__ float g_mask[NUV];
static __device__ float g_thr;
static __device__ unsigned g_cless;
static __device__ int g_split, g_lc, g_kc;   // boundary split-pair info
static __device__ float g_cu[NU], g_su[NU], g_cv[NV], g_sv[NV];
static __device__ float g_corr_r[NIMG], g_corr_i[NIMG];
static __device__ float g_B2[(size_t)GK * NC];   // 37.9 MB  (T transposed)
static __device__ float g_P[(size_t)GK * NC];    // 37.9 MB  (masked F)
static __device__ float g_Q[(size_t)MALL * QW];  // 40.9 MB  (Z, padded)

// ---------------- exact-ish trig helpers (double, argument-reduced) --------
__device__ __forceinline__ float tcos(int num, int den) {
    double a = 2.0 * (double)(num % den) / (double)den;
    return (float)cospi(a);
}
__device__ __forceinline__ float tsin(int num, int den) {
    double a = 2.0 * (double)(num % den) / (double)den;
    return (float)sinpi(a);
}

// ---------------- constant table builder -----------------------------------
__global__ void k_tables() {
    const int total = NV * TW2 + TW2 * NV + 2 * GK * GK;
    for (int idx = blockIdx.x * blockDim.x + threadIdx.x; idx < total;
         idx += gridDim.x * blockDim.x) {
        int i = idx;
        if (i < NV * TW2) {  // E1 [v][j]
            int v = i / TW2, j = i % TW2;
            g_E1[i] = (j < KH) ? tcos(v * j, NV) : -tsin(v * (j - KH), NV);
            continue;
        }
        i -= NV * TW2;
        if (i < TW2 * NV) {  // E4 [kk][v] with fold weights
            int kk = i / NV, v = i % NV;
            if (kk < KH) {
                float w = (kk == 0 || kk == 88) ? 1.f : 2.f;
                g_E4[kk * NV + v] = w * tcos(kk * v, NV);
            } else {
                int k = kk - KH;
                float w = (k == 0 || k == 88) ? 1.f : 2.f;
                g_E4[kk * NV + v] = -w * tsin(k * v, NV);
            }
            continue;
        }
        i -= TW2 * NV;
        if (i < GK * GK) {  // Gz
            int m = i / GK, kk = i % GK;
            int l = (m < NU) ? m : m - NU;
            int u = (kk < NU) ? kk : kk - NU;
            float c = tcos(l * u, NU), s = tsin(l * u, NU);
            g_Gz[i] = (m < NU) ? ((kk < NU) ? c : s) : ((kk < NU) ? -s : c);
            continue;
        }
        i -= GK * GK;
        {   // Gq
            int m = i / GK, kk = i % GK;
            int l = (m < NU) ? m : m - NU;
            int u = (kk < NU) ? kk : kk - NU;
            float c = tcos(l * u, NU), s = tsin(l * u, NU);
            g_Gq[i] = (m < NU) ? ((kk < NU) ? c : -s) : ((kk < NU) ? s : c);
        }
    }
}

// ---------------- r = Re(dft2d(sk2d)), canonicalized (pairs bit-identical) -
__global__ void k_r(const float* __restrict__ kern) {
    int idx = blockIdx.x * blockDim.x + threadIdx.x;
    if (idx >= NUV) return;
    int l = idx / NV, k = idx % NV;
    int lp = (NU - l) % NU, kp = (NV - k) % NV;
    if (lp < l || (lp == l && kp < k)) { l = lp; k = kp; }
    double s = 0.0;
#pragma unroll
    for (int m = 0; m < 6; ++m) {
#pragma unroll
        for (int n = 0; n < 6; ++n) {
            int km = (m < 3) ? m : 5 - m;
            int kn = (n < 3) ? n : 5 - n;
            float p = kern[km * 3 + kn];
            double ang = 2.0 * ((double)((k * m) % NV) / (double)NV +
                                (double)((l * n) % NU) / (double)NU);
            s += (double)p * cospi(ang);
        }
    }
    g_r[idx] = (float)(s / 36.0);
}

// ---------------- exact k-th order statistic (radix select) ----------------
__device__ __forceinline__ unsigned key_of(float f) {
    unsigned u = __float_as_uint(f);
    return (u & 0x80000000u) ? ~u : (u | 0x80000000u);
}

__global__ void k_select() {
    __shared__ unsigned hist[256];
    __shared__ unsigned s_prefix, s_want;
    if (threadIdx.x == 0) { s_prefix = 0u; s_want = (unsigned)RANK; }
    __syncthreads();
    for (int pass = 0; pass < 4; ++pass) {
        int shift = 24 - 8 * pass;
        hist[threadIdx.x] = 0u;
        __syncthreads();
        unsigned prefix = s_prefix;
        unsigned hmask = (pass == 0) ? 0u : (0xFFFFFFFFu << (shift + 8));
        for (int i = threadIdx.x; i < NUV; i += 256) {
            unsigned key = key_of(g_r[i]);
            if ((key & hmask) == (prefix & hmask))
                atomicAdd(&hist[(key >> shift) & 255u], 1u);
        }
        __syncthreads();
        if (threadIdx.x == 0) {
            unsigned want = s_want, cum = 0; int b = 0;
            for (; b < 256; ++b) {
                if (cum + hist[b] > want) break;
                cum += hist[b];
            }
            s_prefix = prefix | ((unsigned)b << shift);
            s_want = want - cum;
        }
        __syncthreads();
    }
    if (threadIdx.x == 0) {
        unsigned kf = s_prefix;
        g_thr = __uint_as_float((kf & 0x80000000u) ? (kf ^ 0x80000000u) : ~kf);
        g_cless = 0u;   // reset for k_count
        g_split = 0;    // reset split detector (graph replay safe)
    }
}

__global__ void k_count() {
    int idx = blockIdx.x * blockDim.x + threadIdx.x;
    if (idx >= NUV) return;
    float thr = g_thr;
    unsigned ballot = __ballot_sync(0xFFFFFFFFu, g_r[idx] < thr);
    if ((threadIdx.x & 31) == 0) atomicAdd(&g_cless, (unsigned)__popc(ballot));
}

// mask: exclude exactly KEXCL smallest; ties at thr by linear-index order
__global__ void k_mask() {
    int idx = blockIdx.x * blockDim.x + threadIdx.x;
    if (idx >= NUV) return;
    float thr = g_thr;
    float v = g_r[idx];
    float m;
    if (v > thr) m = 1.f;
    else if (v < thr) m = 0.f;
    else {
        int budget = (int)(KEXCL - g_cless);
        int rank = 0;
        for (int j = 0; j < idx; ++j)
            if (g_r[j] == thr) ++rank;
        m = (rank >= budget) ? 1.f : 0.f;
    }
    g_mask[idx] = m;
}

// ---------------- split-pair detection + theta tables ----------------------
// If the boundary excluded a single member of a conjugate pair (k not in
// {0,88}), the fold can't represent it: zero the canonical bin and record it
// for a rank-1 correction in stage 4 (output-invariant to member choice).
__global__ void k_detect() {
    const int tot = NU * 87;
    for (int i = threadIdx.x; i < tot; i += 256) {
        int l = i / 87, k = 1 + i % 87;
        float a = g_mask[l * NV + k];
        int lp = (NU - l) % NU, kp = NV - k;
        float b = g_mask[lp * NV + kp];
        if (a != b) { g_lc = l; g_kc = k; g_split = 1; }
    }
    __syncthreads();
    int sp = g_split;
    int lc = g_lc, kc = g_kc;
    if (sp && threadIdx.x == 0) g_mask[lc * NV + kc] = 0.f;
    for (int u = threadIdx.x; u < NU; u += 256) {
        g_cu[u] = sp ? tcos(u * lc, NU) : 0.f;
        g_su[u] = sp ? tsin(u * lc, NU) : 0.f;
    }
    for (int v = threadIdx.x; v < NV; v += 256) {
        g_cv[v] = sp ? tcos(v * kc, NV) : 0.f;
        g_sv[v] = sp ? tsin(v * kc, NV) : 0.f;
    }
}

// per-image unmasked F at the split bin: c = (Gz . T)[lc / 208+lc][img,kc]
__global__ void k_corr() {
    int img = threadIdx.x;
    float cr = 0.f, ci = 0.f;
    if (g_split) {
        int lc = g_lc, kc = g_kc;
        for (int kk = 0; kk < GK; ++kk) {
            float t = g_B2[(size_t)kk * NC + img * KH + kc];
            cr += g_Gz[lc * GK + kk] * t;
            ci += g_Gz[(NU + lc) * GK + kk] * t;
        }
    }
    g_corr_r[img] = cr;
    g_corr_i[img] = ci;
}

// ---------------- 128x64 / 8x4 fp32 GEMM stages ----------------------------

// Stage 1: [53248 x 178] = X[53248 x 176] * E1[176 x 178]; store transposed
// into B2[416 x 22784] (rows: Re u / Im u+208; cols: img*89 + k)
__global__ void __launch_bounds__(256) k_g1(const float* __restrict__ X) {
    __shared__ float As[16][128];
    __shared__ float Bs[16][64];
    const int n0 = blockIdx.x * 64, m0 = blockIdx.y * 128;
    const int t = threadIdx.x, tx = t & 15, ty = t >> 4;
    float acc[8][4] = {};
    for (int k0 = 0; k0 < NV; k0 += 16) {
#pragma unroll
        for (int j = 0; j < 8; ++j) {
            int idx = t + 256 * j; int m = idx >> 4, kk = idx & 15;
            As[kk][m] = X[(size_t)(m0 + m) * NV + k0 + kk];
        }
#pragma unroll
        for (int j = 0; j < 4; ++j) {
            int idx = t + 256 * j; int kk = idx >> 6, n = idx & 63;
            int gn = n0 + n;
            Bs[kk][n] = (gn < TW2) ? g_E1[(k0 + kk) * TW2 + gn] : 0.f;
        }
        __syncthreads();
#pragma unroll
        for (int kk = 0; kk < 16; ++kk) {
            float4 a0 = *(const float4*)&As[kk][ty * 8];
            float4 a1 = *(const float4*)&As[kk][ty * 8 + 4];
            float4 b  = *(const float4*)&Bs[kk][tx * 4];
            float av[8] = {a0.x,a0.y,a0.z,a0.w,a1.x,a1.y,a1.z,a1.w};
            float bv[4] = {b.x,b.y,b.z,b.w};
#pragma unroll
            for (int i = 0; i < 8; ++i)
#pragma unroll
                for (int jj = 0; jj < 4; ++jj) acc[i][jj] += av[i] * bv[jj];
        }
        __syncthreads();
    }
#pragma unroll
    for (int i = 0; i < 8; ++i) {
        int gm = m0 + ty * 8 + i;
        int img = gm / NU, u = gm - img * NU;
#pragma unroll
        for (int jj = 0; jj < 4; ++jj) {
            int gn = n0 + tx * 4 + jj;
            if (gn < KH)
                g_B2[(size_t)u * NC + img * KH + gn] = acc[i][jj];
            else if (gn < TW2)
                g_B2[(size_t)(NU + u) * NC + img * KH + (gn - KH)] = acc[i][jj];
        }
    }
}

// Stage 2: P[416 x 22784] = mask o ( Gz[416x416] * B2[416 x 22784] )
__global__ void __launch_bounds__(256) k_g2() {
    __shared__ float As[16][128];
    __shared__ float Bs[16][64];
    const int n0 = blockIdx.x * 64, m0 = blockIdx.y * 128;
    const int t = threadIdx.x, tx = t & 15, ty = t >> 4;
    float acc[8][4] = {};
    for (int k0 = 0; k0 < GK; k0 += 16) {
#pragma unroll
        for (int j = 0; j < 8; ++j) {
            int idx = t + 256 * j; int m = idx >> 4, kk = idx & 15;
            int gm = m0 + m;
            As[kk][m] = (gm < GK) ? g_Gz[gm * GK + k0 + kk] : 0.f;
        }
#pragma unroll
        for (int j = 0; j < 4; ++j) {
            int idx = t + 256 * j; int kk = idx >> 6, n = idx & 63;
            Bs[kk][n] = g_B2[(size_t)(k0 + kk) * NC + n0 + n];
        }
        __syncthreads();
#pragma unroll
        for (int kk = 0; kk < 16; ++kk) {
            float4 a0 = *(const float4*)&As[kk][ty * 8];
            float4 a1 = *(const float4*)&As[kk][ty * 8 + 4];
            float4 b  = *(const float4*)&Bs[kk][tx * 4];
            float av[8] = {a0.x,a0.y,a0.z,a0.w,a1.x,a1.y,a1.z,a1.w};
            float bv[4] = {b.x,b.y,b.z,b.w};
#pragma unroll
            for (int i = 0; i < 8; ++i)
#pragma unroll
                for (int jj = 0; jj < 4; ++jj) acc[i][jj] += av[i] * bv[jj];
        }
        __syncthreads();
    }
#pragma unroll
    for (int i = 0; i < 8; ++i) {
        int gm = m0 + ty * 8 + i;
        if (gm >= GK) continue;
        int l = (gm < NU) ? gm : gm - NU;
#pragma unroll
        for (int jj = 0; jj < 4; ++jj) {
            int c = n0 + tx * 4 + jj;
            int k = c % KH;
            g_P[(size_t)gm * NC + c] = acc[i][jj] * g_mask[l * NV + k];
        }
    }
}

// Stage 3: Z = Gq[416x416] * P -> Q[(img,u) x 192] (cols k / 89+k)
__global__ void __launch_bounds__(256) k_g3() {
    __shared__ float As[16][128];
    __shared__ float Bs[16][64];
    const int n0 = blockIdx.x * 64, m0 = blockIdx.y * 128;
    const int t = threadIdx.x, tx = t & 15, ty = t >> 4;
    float acc[8][4] = {};
    for (int k0 = 0; k0 < GK; k0 += 16) {
#pragma unroll
        for (int j = 0; j < 8; ++j) {
            int idx = t + 256 * j; int m = idx >> 4, kk = idx & 15;
            int gm = m0 + m;
            As[kk][m] = (gm < GK) ? g_Gq[gm * GK + k0 + kk] : 0.f;
        }
#pragma unroll
        for (int j = 0; j < 4; ++j) {
            int idx = t + 256 * j; int kk = idx >> 6, n = idx & 63;
            Bs[kk][n] = g_P[(size_t)(k0 + kk) * NC + n0 + n];
        }
        __syncthreads();
#pragma unroll
        for (int kk = 0; kk < 16; ++kk) {
            float4 a0 = *(const float4*)&As[kk][ty * 8];
            float4 a1 = *(const float4*)&As[kk][ty * 8 + 4];
            float4 b  = *(const float4*)&Bs[kk][tx * 4];
            float av[8] = {a0.x,a0.y,a0.z,a0.w,a1.x,a1.y,a1.z,a1.w};
            float bv[4] = {b.x,b.y,b.z,b.w};
#pragma unroll
            for (int i = 0; i < 8; ++i)
#pragma unroll
                for (int jj = 0; jj < 4; ++jj) acc[i][jj] += av[i] * bv[jj];
        }
        __syncthreads();
    }
#pragma unroll
    for (int i = 0; i < 8; ++i) {
        int gm = m0 + ty * 8 + i;
        if (gm >= GK) continue;
        int u = (gm < NU) ? gm : gm - NU;
#pragma unroll
        for (int jj = 0; jj < 4; ++jj) {
            int c = n0 + tx * 4 + jj;
            int img = c / KH, k = c - img * KH;
            int col = (gm < NU) ? k : KH + k;
            g_Q[((size_t)img * NU + u) * QW + col] = acc[i][jj];
        }
    }
}

// Stage 4: y = Q[53248 x 192] * E4[192 x 176]; out = |y + corr| / 36608
__global__ void __launch_bounds__(256) k_g4(float* __restrict__ out) {
    __shared__ float As[16][128];
    __shared__ float Bs[16][64];
    const int n0 = blockIdx.x * 64, m0 = blockIdx.y * 128;
    const int t = threadIdx.x, tx = t & 15, ty = t >> 4;
    float acc[8][4] = {};
    for (int k0 = 0; k0 < QW; k0 += 16) {
#pragma unroll
        for (int j = 0; j < 8; ++j) {
            int idx = t + 256 * j; int m = idx >> 4, kk = idx & 15;
            As[kk][m] = g_Q[(size_t)(m0 + m) * QW + k0 + kk];
        }
#pragma unroll
        for (int j = 0; j < 4; ++j) {
            int idx = t + 256 * j; int kk = idx >> 6, n = idx & 63;
            int gn = n0 + n;
            Bs[kk][n] = (gn < NV) ? g_E4[(k0 + kk) * NV + gn] : 0.f;
        }
        __syncthreads();
#pragma unroll
        for (int kk = 0; kk < 16; ++kk) {
            float4 a0 = *(const float4*)&As[kk][ty * 8];
            float4 a1 = *(const float4*)&As[kk][ty * 8 + 4];
            float4 b  = *(const float4*)&Bs[kk][tx * 4];
            float av[8] = {a0.x,a0.y,a0.z,a0.w,a1.x,a1.y,a1.z,a1.w};
            float bv[4] = {b.x,b.y,b.z,b.w};
#pragma unroll
            for (int i = 0; i < 8; ++i)
#pragma unroll
                for (int jj = 0; jj < 4; ++jj) acc[i][jj] += av[i] * bv[jj];
        }
        __syncthreads();
    }
    const float scale = 1.0f / (float)NUV;
#pragma unroll
    for (int i = 0; i < 8; ++i) {
        int gm = m0 + ty * 8 + i;
        int img = gm / NU, u = gm - img * NU;
        float cr = g_corr_r[img], ci = g_corr_i[img];
        float cu = g_cu[u], su = g_su[u];
#pragma unroll
        for (int jj = 0; jj < 4; ++jj) {
            int gn = n0 + tx * 4 + jj;
            if (gn < NV) {
                float cv = g_cv[gn], sv = g_sv[gn];
                float ct = cu * cv - su * sv;
                float st = su * cv + cu * sv;
                float yr = acc[i][jj] + cr * ct - ci * st;
                float yi = cr * st + ci * ct;
                out[(size_t)gm * NV + gn] = sqrtf(yr * yr + yi * yi) * scale;
            }
        }
    }
}

// ---------------- launch -----------------------------------------------------
extern "C" void kernel_launch(void* const* d_in, const int* in_sizes, int n_in,
                              void* d_out, int out_size) {
    const float* x = nullptr;
    const float* kern = nullptr;
    for (int i = 0; i < n_in; ++i) {
        if (in_sizes[i] == 32 * 8 * NU * NV) x = (const float*)d_in[i];
        else if (in_sizes[i] == 9) kern = (const float*)d_in[i];
    }
    float* out = (float*)d_out;

    k_tables<<<512, 256>>>();
    k_r<<<(NUV + 255) / 256, 256>>>(kern);
    k_select<<<1, 256>>>();
    k_count<<<(NUV + 255) / 256, 256>>>();
    k_mask<<<(NUV + 255) / 256, 256>>>();
    k_detect<<<1, 256>>>();

    k_g1<<<dim3(3, MALL / 128), 256>>>(x);
    k_corr<<<1, 256>>>();
    k_g2<<<dim3(NC / 64, 4), 256>>>();
    k_g3<<<dim3(NC / 64, 4), 256>>>();
    k_g4<<<dim3(3, MALL / 128), 256>>>(out);
}